// round 8
// baseline (speedup 1.0000x reference)
#include <cuda_runtime.h>
#include <math.h>

// Problem constants
//   outputs/targets:           [4, 3, 256, 256]  -> 786432 floats
//   output/target features:    [4, 256, 64, 64]  -> B=4, C=256, N=4096
#define Bn   4
#define Cn   256
#define Nn   4096
#define IMG_ELEMS  786432
#define FEAT_ELEMS 4194304
#define EPS1 1e-8f
#define EPS2 1e-5f

// ---------------- device scratch (allocation-free: static globals) ----------
static __device__ float  g_X[Bn * Nn * Cn];          // centered out-features [b][n][c]
static __device__ float  g_Y[Bn * Nn * Cn];          // centered tgt-features [b][n][c]
static __device__ float  g_mean[2][Bn * Cn];         // per-(b,c) means, [0]=out [1]=tgt
static __device__ float  g_xn[Bn * Nn];              // row norms of X
static __device__ float  g_yn[Bn * Nn];              // row norms of Y
static __device__ float  g_cos[(size_t)Bn * Nn * Nn];// 256 MB cosine matrix [b][x][y]
static __device__ float  g_pS[Bn * Nn];              // per-row scale s = 1/(dmin+eps2)
static __device__ float  g_pA[Bn * Nn];              // per-row affine (1-s) - log(rowsum)
static __device__ float  g_cmax[8 * Bn * Nn];        // partial col maxima (8 x-chunks)
static __device__ double g_msep[2][512];             // MSE block partials

// ---------------- f32x2 packed-FMA helpers ----------------------------------
__device__ __forceinline__ unsigned long long pk2(float lo, float hi) {
    unsigned long long r;
    asm("mov.b64 %0, {%1,%2};" : "=l"(r)
        : "r"(__float_as_uint(lo)), "r"(__float_as_uint(hi)));
    return r;
}
__device__ __forceinline__ unsigned long long bc2(float v) { return pk2(v, v); }
__device__ __forceinline__ void fma2(unsigned long long& d, unsigned long long a,
                                     unsigned long long b) {
    asm("fma.rn.f32x2 %0, %1, %2, %3;" : "=l"(d) : "l"(a), "l"(b), "l"(d));
}
__device__ __forceinline__ void unpk2(unsigned long long p, float& lo, float& hi) {
    unsigned int l, h;
    asm("mov.b64 {%0,%1}, %2;" : "=r"(l), "=r"(h) : "l"(p));
    lo = __uint_as_float(l);
    hi = __uint_as_float(h);
}

// ---------------- 1. MSE partials (deterministic two-stage) ------------------
__global__ void __launch_bounds__(256) mse_kernel(const float* __restrict__ o,
                                                  const float* __restrict__ t,
                                                  const float* __restrict__ of,
                                                  const float* __restrict__ tf) {
    const int which = blockIdx.y;
    const float* a = which ? of : o;
    const float* c = which ? tf : t;
    const int n = which ? FEAT_ELEMS : IMG_ELEMS;
    double s = 0.0;
    for (int i = blockIdx.x * 256 + threadIdx.x; i < n; i += 512 * 256) {
        float d = a[i] - c[i];
        s += (double)d * (double)d;
    }
    __shared__ double sh[256];
    sh[threadIdx.x] = s;
    __syncthreads();
    for (int st = 128; st > 0; st >>= 1) {
        if (threadIdx.x < st) sh[threadIdx.x] += sh[threadIdx.x + st];
        __syncthreads();
    }
    if (threadIdx.x == 0) g_msep[which][blockIdx.x] = sh[0];
}

// ---------------- 2. per-(b,c) means over N positions ------------------------
__global__ void __launch_bounds__(256) mean_kernel(const float* __restrict__ of,
                                                   const float* __restrict__ tf) {
    const float* src = blockIdx.y ? tf : of;
    const int bc = blockIdx.x;  // b*Cn + c
    const float* p = src + (size_t)bc * Nn;
    float s = 0.f;
    for (int i = threadIdx.x; i < Nn; i += 256) s += p[i];
    __shared__ float sh[256];
    sh[threadIdx.x] = s;
    __syncthreads();
    for (int st = 128; st > 0; st >>= 1) {
        if (threadIdx.x < st) sh[threadIdx.x] += sh[threadIdx.x + st];
        __syncthreads();
    }
    if (threadIdx.x == 0) g_mean[blockIdx.y][bc] = sh[0] * (1.f / Nn);
}

// ---------------- 3. transpose [C][N] -> [N][C] with centering ---------------
__global__ void __launch_bounds__(256) transpose_kernel(const float* __restrict__ of,
                                                        const float* __restrict__ tf) {
    const int tz = blockIdx.z;
    const int tensor = tz >> 2;
    const int b = tz & 3;
    const float* src = (tensor ? tf : of) + (size_t)b * Cn * Nn;
    float* dst = (tensor ? g_Y : g_X) + (size_t)b * Nn * Cn;
    const float* mean = g_mean[tensor] + b * Cn;
    __shared__ float tile[32][33];
    const int tx = threadIdx.x, ty = threadIdx.y;  // 32 x 8
    const int n0 = blockIdx.x * 32, c0 = blockIdx.y * 32;
#pragma unroll
    for (int j = 0; j < 4; j++) {
        int c = c0 + ty + j * 8;
        tile[ty + j * 8][tx] = src[(size_t)c * Nn + n0 + tx] - mean[c];
    }
    __syncthreads();
#pragma unroll
    for (int j = 0; j < 4; j++) {
        int n = n0 + ty + j * 8;
        dst[(size_t)n * Cn + c0 + tx] = tile[tx][ty + j * 8];
    }
}

// ---------------- 4. per-row L2 norms ---------------------------------------
__global__ void __launch_bounds__(256) norm_kernel() {
    const int tensor = blockIdx.y;
    const float* X = tensor ? g_Y : g_X;
    float* out = tensor ? g_yn : g_xn;
    const int warp = threadIdx.x >> 5, lane = threadIdx.x & 31;
    const int r = blockIdx.x * 8 + warp;  // 0..16383
    const float4* p = (const float4*)(X + (size_t)r * Cn);
    float s = 0.f;
    float4 v = p[lane];
    s += v.x * v.x + v.y * v.y + v.z * v.z + v.w * v.w;
    v = p[lane + 32];
    s += v.x * v.x + v.y * v.y + v.z * v.z + v.w * v.w;
    for (int o = 16; o; o >>= 1) s += __shfl_xor_sync(0xffffffffu, s, o);
    if (lane == 0) out[r] = sqrtf(s);
}

// ---------------- 5. GEMM: cos[b][x][y] = <X_x,Y_y>/(xn*yn+eps1) -------------
// 128x128 tile, BK=8, 256 threads, 8x8 per thread, f32x2 packed FMAs,
// double-buffered smem.
__global__ void __launch_bounds__(256, 1) gemm_kernel() {
    const int b = blockIdx.z;
    const float* __restrict__ A = g_X + (size_t)b * (Nn * Cn);
    const float* __restrict__ Bm = g_Y + (size_t)b * (Nn * Cn);
    float* __restrict__ C = g_cos + (size_t)b * ((size_t)Nn * Nn);
    const int tid = threadIdx.x;
    const int rowBase = blockIdx.y * 128, colBase = blockIdx.x * 128;
    __shared__ float As[2][8][128];
    __shared__ float Bs[2][8][128];
    const int lr = tid >> 1;
    const int lc = (tid & 1) << 2;
    const float* Ap = A + (size_t)(rowBase + lr) * Cn + lc;
    const float* Bp = Bm + (size_t)(colBase + lr) * Cn + lc;

    float4 ra = *(const float4*)Ap;
    float4 rb = *(const float4*)Bp;
    As[0][lc + 0][lr] = ra.x; As[0][lc + 1][lr] = ra.y;
    As[0][lc + 2][lr] = ra.z; As[0][lc + 3][lr] = ra.w;
    Bs[0][lc + 0][lr] = rb.x; Bs[0][lc + 1][lr] = rb.y;
    Bs[0][lc + 2][lr] = rb.z; Bs[0][lc + 3][lr] = rb.w;
    __syncthreads();

    unsigned long long acc[8][4];
#pragma unroll
    for (int i = 0; i < 8; i++)
#pragma unroll
        for (int j = 0; j < 4; j++) acc[i][j] = 0ull;

    const int trow = tid >> 4, tcol = tid & 15;
    const int ar = trow << 3, bcc = tcol << 3;

    for (int kt = 0; kt < 32; kt++) {
        const int cur = kt & 1;
        float4 na, nb;
        if (kt < 31) {
            na = *(const float4*)(Ap + (kt + 1) * 8);
            nb = *(const float4*)(Bp + (kt + 1) * 8);
        }
#pragma unroll
        for (int k = 0; k < 8; k++) {
            const float4 a0 = *(const float4*)&As[cur][k][ar];
            const float4 a1 = *(const float4*)&As[cur][k][ar + 4];
            const ulonglong2 b0 = *(const ulonglong2*)&Bs[cur][k][bcc];
            const ulonglong2 b1 = *(const ulonglong2*)&Bs[cur][k][bcc + 4];
            unsigned long long av;
            av = bc2(a0.x);
            fma2(acc[0][0], av, b0.x); fma2(acc[0][1], av, b0.y);
            fma2(acc[0][2], av, b1.x); fma2(acc[0][3], av, b1.y);
            av = bc2(a0.y);
            fma2(acc[1][0], av, b0.x); fma2(acc[1][1], av, b0.y);
            fma2(acc[1][2], av, b1.x); fma2(acc[1][3], av, b1.y);
            av = bc2(a0.z);
            fma2(acc[2][0], av, b0.x); fma2(acc[2][1], av, b0.y);
            fma2(acc[2][2], av, b1.x); fma2(acc[2][3], av, b1.y);
            av = bc2(a0.w);
            fma2(acc[3][0], av, b0.x); fma2(acc[3][1], av, b0.y);
            fma2(acc[3][2], av, b1.x); fma2(acc[3][3], av, b1.y);
            av = bc2(a1.x);
            fma2(acc[4][0], av, b0.x); fma2(acc[4][1], av, b0.y);
            fma2(acc[4][2], av, b1.x); fma2(acc[4][3], av, b1.y);
            av = bc2(a1.y);
            fma2(acc[5][0], av, b0.x); fma2(acc[5][1], av, b0.y);
            fma2(acc[5][2], av, b1.x); fma2(acc[5][3], av, b1.y);
            av = bc2(a1.z);
            fma2(acc[6][0], av, b0.x); fma2(acc[6][1], av, b0.y);
            fma2(acc[6][2], av, b1.x); fma2(acc[6][3], av, b1.y);
            av = bc2(a1.w);
            fma2(acc[7][0], av, b0.x); fma2(acc[7][1], av, b0.y);
            fma2(acc[7][2], av, b1.x); fma2(acc[7][3], av, b1.y);
        }
        if (kt < 31) {
            const int nxt = cur ^ 1;
            As[nxt][lc + 0][lr] = na.x; As[nxt][lc + 1][lr] = na.y;
            As[nxt][lc + 2][lr] = na.z; As[nxt][lc + 3][lr] = na.w;
            Bs[nxt][lc + 0][lr] = nb.x; Bs[nxt][lc + 1][lr] = nb.y;
            Bs[nxt][lc + 2][lr] = nb.z; Bs[nxt][lc + 3][lr] = nb.w;
            __syncthreads();
        }
    }

    // epilogue: normalize to cosine, vectorized stores
    const float* xn = g_xn + (b << 12);
    const float* yn = g_yn + (b << 12);
    float ynv[8];
#pragma unroll
    for (int j = 0; j < 8; j++) ynv[j] = yn[colBase + bcc + j];
#pragma unroll
    for (int i = 0; i < 8; i++) {
        const int x = rowBase + ar + i;
        const float xv = xn[x];
        float out[8];
#pragma unroll
        for (int j = 0; j < 4; j++) {
            float lo, hi;
            unpk2(acc[i][j], lo, hi);
            out[2 * j]     = lo / (xv * ynv[2 * j] + EPS1);
            out[2 * j + 1] = hi / (xv * ynv[2 * j + 1] + EPS1);
        }
        float* cp = C + (size_t)x * Nn + colBase + bcc;
        *(float4*)cp       = make_float4(out[0], out[1], out[2], out[3]);
        *(float4*)(cp + 4) = make_float4(out[4], out[5], out[6], out[7]);
    }
}

// ---------------- 6. row pass: rowmax(cos), softmax denom --------------------
// d = 1-cos; dmin = 1-cosmax; s = 1/(dmin+eps2)
// w_y = exp(1 - d_y*s) = exp((1-s) + cos_y*s); store s and (1-s)-log(sum w)
__global__ void __launch_bounds__(256) rowpass_kernel() {
    const int r = blockIdx.x;  // b*Nn + x
    const float* row = g_cos + (size_t)r * Nn;
    __shared__ float sh[Nn];
    __shared__ float red[256];
    const int tid = threadIdx.x;
    float m = -1e30f;
#pragma unroll
    for (int j = 0; j < 16; j++) {
        float v = row[tid + (j << 8)];
        sh[tid + (j << 8)] = v;
        m = fmaxf(m, v);
    }
    red[tid] = m;
    __syncthreads();
    for (int st = 128; st > 0; st >>= 1) {
        if (tid < st) red[tid] = fmaxf(red[tid], red[tid + st]);
        __syncthreads();
    }
    const float cmax = red[0];
    __syncthreads();
    const float s = 1.f / (1.f - cmax + EPS2);
    const float a = 1.f - s;
    float sum = 0.f;
#pragma unroll
    for (int j = 0; j < 16; j++) sum += __expf(fmaf(sh[tid + (j << 8)], s, a));
    red[tid] = sum;
    __syncthreads();
    for (int st = 128; st > 0; st >>= 1) {
        if (tid < st) red[tid] += red[tid + st];
        __syncthreads();
    }
    if (tid == 0) {
        g_pS[r] = s;
        g_pA[r] = a - logf(red[0]);
    }
}

// ---------------- 7. column pass: partial max over x (log-domain) ------------
// log c[x][y] = cos*s_x + A_x  -> max over x chunk of 512, no exp per element
__global__ void __launch_bounds__(256) colpass_kernel() {
    const int y = (blockIdx.x << 8) + threadIdx.x;  // 0..4095
    const int chunk = blockIdx.y;                   // 0..7
    const int b = blockIdx.z;                       // 0..3
    __shared__ float ss[512], sa[512];
    const int r0 = (b << 12) + (chunk << 9);
    for (int i = threadIdx.x; i < 512; i += 256) {
        ss[i] = g_pS[r0 + i];
        sa[i] = g_pA[r0 + i];
    }
    __syncthreads();
    const float* base = g_cos + ((size_t)b << 24) + ((size_t)chunk << 21) + y;
    float m = -1e30f;
#pragma unroll 8
    for (int x = 0; x < 512; x++) {
        m = fmaxf(m, fmaf(base[(size_t)x << 12], ss[x], sa[x]));
    }
    g_cmax[(chunk << 14) + (b << 12) + y] = m;
}

// ---------------- 8. final: CS, MSEs, loss -----------------------------------
__global__ void __launch_bounds__(256) final_kernel(float* __restrict__ out) {
    const int tid = threadIdx.x;
    double cs = 0.0;
    for (int i = tid; i < Bn * Nn; i += 256) {
        float m = -1e30f;
#pragma unroll
        for (int ch = 0; ch < 8; ch++) m = fmaxf(m, g_cmax[(ch << 14) + i]);
        cs += exp((double)m);
    }
    double m1 = 0.0, m2 = 0.0;
    for (int i = tid; i < 512; i += 256) {
        m1 += g_msep[0][i];
        m2 += g_msep[1][i];
    }
    __shared__ double sh[3][256];
    sh[0][tid] = cs; sh[1][tid] = m1; sh[2][tid] = m2;
    __syncthreads();
    for (int st = 128; st > 0; st >>= 1) {
        if (tid < st) {
            sh[0][tid] += sh[0][tid + st];
            sh[1][tid] += sh[1][tid + st];
            sh[2][tid] += sh[2][tid + st];
        }
        __syncthreads();
    }
    if (tid == 0) {
        double CS = sh[0][0] / (double)(Bn * Nn);
        double mse1 = sh[1][0] / (double)IMG_ELEMS;
        double perc = sh[2][0] / (double)FEAT_ELEMS;
        out[0] = (float)(mse1 - log(CS) + 0.02 * perc);
    }
}

// ---------------- launch ------------------------------------------------------
extern "C" void kernel_launch(void* const* d_in, const int* in_sizes, int n_in,
                              void* d_out, int out_size) {
    const float* outputs = (const float*)d_in[0];
    const float* targets = (const float*)d_in[1];
    const float* of = (const float*)d_in[2];
    const float* tf = (const float*)d_in[3];
    float* out = (float*)d_out;

    mse_kernel<<<dim3(512, 2), 256>>>(outputs, targets, of, tf);
    mean_kernel<<<dim3(Bn * Cn, 2), 256>>>(of, tf);
    transpose_kernel<<<dim3(Nn / 32, Cn / 32, 2 * Bn), dim3(32, 8)>>>(of, tf);
    norm_kernel<<<dim3(Bn * Nn / 8, 2), 256>>>();
    gemm_kernel<<<dim3(Nn / 128, Nn / 128, Bn), 256>>>();
    rowpass_kernel<<<Bn * Nn, 256>>>();
    colpass_kernel<<<dim3(Nn / 256, 8, Bn), 256>>>();
    final_kernel<<<1, 256>>>(out);
}

// round 9
// speedup vs baseline: 1.0012x; 1.0012x over previous
#include <cuda_runtime.h>
#include <math.h>

// Problem constants
//   outputs/targets:           [4, 3, 256, 256]  -> 786432 floats
//   output/target features:    [4, 256, 64, 64]  -> B=4, C=256, N=4096
#define Bn   4
#define Cn   256
#define Nn   4096
#define IMG_ELEMS  786432
#define FEAT_ELEMS 4194304
#define EPS1 1e-8f
#define EPS2 1e-5f

// ---------------- device scratch (allocation-free: static globals) ----------
static __device__ float  g_X[Bn * Nn * Cn];          // centered out-features [b][n][c]
static __device__ float  g_Y[Bn * Nn * Cn];          // centered tgt-features [b][n][c]
static __device__ float  g_mean[2][Bn * Cn];         // per-(b,c) means, [0]=out [1]=tgt
static __device__ float  g_xn[Bn * Nn];              // row norms of X
static __device__ float  g_yn[Bn * Nn];              // row norms of Y
static __device__ float  g_cos[(size_t)Bn * Nn * Nn];// 256 MB cosine matrix [b][x][y]
static __device__ float  g_pS[Bn * Nn];              // per-row scale s = 1/(dmin+eps2)
static __device__ float  g_pA[Bn * Nn];              // per-row affine (1-s) - log(rowsum)
static __device__ float  g_cmax[8 * Bn * Nn];        // partial col maxima (8 x-chunks)
static __device__ double g_msep[2][512];             // MSE block partials

// ---------------- f32x2 packed-FMA helpers ----------------------------------
__device__ __forceinline__ unsigned long long pk2(float lo, float hi) {
    unsigned long long r;
    asm("mov.b64 %0, {%1,%2};" : "=l"(r)
        : "r"(__float_as_uint(lo)), "r"(__float_as_uint(hi)));
    return r;
}
__device__ __forceinline__ unsigned long long bc2(float v) { return pk2(v, v); }
__device__ __forceinline__ void fma2(unsigned long long& d, unsigned long long a,
                                     unsigned long long b) {
    asm("fma.rn.f32x2 %0, %1, %2, %3;" : "=l"(d) : "l"(a), "l"(b), "l"(d));
}
__device__ __forceinline__ void unpk2(unsigned long long p, float& lo, float& hi) {
    unsigned int l, h;
    asm("mov.b64 {%0,%1}, %2;" : "=r"(l), "=r"(h) : "l"(p));
    lo = __uint_as_float(l);
    hi = __uint_as_float(h);
}

// ---------------- 1. MSE partials (deterministic two-stage) ------------------
__global__ void __launch_bounds__(256) mse_kernel(const float* __restrict__ o,
                                                  const float* __restrict__ t,
                                                  const float* __restrict__ of,
                                                  const float* __restrict__ tf) {
    const int which = blockIdx.y;
    const float* a = which ? of : o;
    const float* c = which ? tf : t;
    const int n = which ? FEAT_ELEMS : IMG_ELEMS;
    double s = 0.0;
    for (int i = blockIdx.x * 256 + threadIdx.x; i < n; i += 512 * 256) {
        float d = a[i] - c[i];
        s += (double)d * (double)d;
    }
    __shared__ double sh[256];
    sh[threadIdx.x] = s;
    __syncthreads();
    for (int st = 128; st > 0; st >>= 1) {
        if (threadIdx.x < st) sh[threadIdx.x] += sh[threadIdx.x + st];
        __syncthreads();
    }
    if (threadIdx.x == 0) g_msep[which][blockIdx.x] = sh[0];
}

// ---------------- 2. per-(b,c) means over N positions ------------------------
__global__ void __launch_bounds__(256) mean_kernel(const float* __restrict__ of,
                                                   const float* __restrict__ tf) {
    const float* src = blockIdx.y ? tf : of;
    const int bc = blockIdx.x;  // b*Cn + c
    const float* p = src + (size_t)bc * Nn;
    float s = 0.f;
    for (int i = threadIdx.x; i < Nn; i += 256) s += p[i];
    __shared__ float sh[256];
    sh[threadIdx.x] = s;
    __syncthreads();
    for (int st = 128; st > 0; st >>= 1) {
        if (threadIdx.x < st) sh[threadIdx.x] += sh[threadIdx.x + st];
        __syncthreads();
    }
    if (threadIdx.x == 0) g_mean[blockIdx.y][bc] = sh[0] * (1.f / Nn);
}

// ---------------- 3. transpose [C][N] -> [N][C] with centering ---------------
__global__ void __launch_bounds__(256) transpose_kernel(const float* __restrict__ of,
                                                        const float* __restrict__ tf) {
    const int tz = blockIdx.z;
    const int tensor = tz >> 2;
    const int b = tz & 3;
    const float* src = (tensor ? tf : of) + (size_t)b * Cn * Nn;
    float* dst = (tensor ? g_Y : g_X) + (size_t)b * Nn * Cn;
    const float* mean = g_mean[tensor] + b * Cn;
    __shared__ float tile[32][33];
    const int tx = threadIdx.x, ty = threadIdx.y;  // 32 x 8
    const int n0 = blockIdx.x * 32, c0 = blockIdx.y * 32;
#pragma unroll
    for (int j = 0; j < 4; j++) {
        int c = c0 + ty + j * 8;
        tile[ty + j * 8][tx] = src[(size_t)c * Nn + n0 + tx] - mean[c];
    }
    __syncthreads();
#pragma unroll
    for (int j = 0; j < 4; j++) {
        int n = n0 + ty + j * 8;
        dst[(size_t)n * Cn + c0 + tx] = tile[tx][ty + j * 8];
    }
}

// ---------------- 4. per-row L2 norms ---------------------------------------
__global__ void __launch_bounds__(256) norm_kernel() {
    const int tensor = blockIdx.y;
    const float* X = tensor ? g_Y : g_X;
    float* out = tensor ? g_yn : g_xn;
    const int warp = threadIdx.x >> 5, lane = threadIdx.x & 31;
    const int r = blockIdx.x * 8 + warp;  // 0..16383
    const float4* p = (const float4*)(X + (size_t)r * Cn);
    float s = 0.f;
    float4 v = p[lane];
    s += v.x * v.x + v.y * v.y + v.z * v.z + v.w * v.w;
    v = p[lane + 32];
    s += v.x * v.x + v.y * v.y + v.z * v.z + v.w * v.w;
    for (int o = 16; o; o >>= 1) s += __shfl_xor_sync(0xffffffffu, s, o);
    if (lane == 0) out[r] = sqrtf(s);
}

// ---------------- 5. GEMM: cos[b][x][y] = <X_x,Y_y>/(xn*yn+eps1) -------------
// 128x128 tile, BK=8, 256 threads, 8x8 per thread, f32x2 packed FMAs,
// double-buffered smem.
__global__ void __launch_bounds__(256, 1) gemm_kernel() {
    const int b = blockIdx.z;
    const float* __restrict__ A = g_X + (size_t)b * (Nn * Cn);
    const float* __restrict__ Bm = g_Y + (size_t)b * (Nn * Cn);
    float* __restrict__ C = g_cos + (size_t)b * ((size_t)Nn * Nn);
    const int tid = threadIdx.x;
    const int rowBase = blockIdx.y * 128, colBase = blockIdx.x * 128;
    __shared__ float As[2][8][128];
    __shared__ float Bs[2][8][128];
    const int lr = tid >> 1;
    const int lc = (tid & 1) << 2;
    const float* Ap = A + (size_t)(rowBase + lr) * Cn + lc;
    const float* Bp = Bm + (size_t)(colBase + lr) * Cn + lc;

    float4 ra = *(const float4*)Ap;
    float4 rb = *(const float4*)Bp;
    As[0][lc + 0][lr] = ra.x; As[0][lc + 1][lr] = ra.y;
    As[0][lc + 2][lr] = ra.z; As[0][lc + 3][lr] = ra.w;
    Bs[0][lc + 0][lr] = rb.x; Bs[0][lc + 1][lr] = rb.y;
    Bs[0][lc + 2][lr] = rb.z; Bs[0][lc + 3][lr] = rb.w;
    __syncthreads();

    unsigned long long acc[8][4];
#pragma unroll
    for (int i = 0; i < 8; i++)
#pragma unroll
        for (int j = 0; j < 4; j++) acc[i][j] = 0ull;

    const int trow = tid >> 4, tcol = tid & 15;
    const int ar = trow << 3, bcc = tcol << 3;

    for (int kt = 0; kt < 32; kt++) {
        const int cur = kt & 1;
        float4 na, nb;
        if (kt < 31) {
            na = *(const float4*)(Ap + (kt + 1) * 8);
            nb = *(const float4*)(Bp + (kt + 1) * 8);
        }
#pragma unroll
        for (int k = 0; k < 8; k++) {
            const float4 a0 = *(const float4*)&As[cur][k][ar];
            const float4 a1 = *(const float4*)&As[cur][k][ar + 4];
            const ulonglong2 b0 = *(const ulonglong2*)&Bs[cur][k][bcc];
            const ulonglong2 b1 = *(const ulonglong2*)&Bs[cur][k][bcc + 4];
            unsigned long long av;
            av = bc2(a0.x);
            fma2(acc[0][0], av, b0.x); fma2(acc[0][1], av, b0.y);
            fma2(acc[0][2], av, b1.x); fma2(acc[0][3], av, b1.y);
            av = bc2(a0.y);
            fma2(acc[1][0], av, b0.x); fma2(acc[1][1], av, b0.y);
            fma2(acc[1][2], av, b1.x); fma2(acc[1][3], av, b1.y);
            av = bc2(a0.z);
            fma2(acc[2][0], av, b0.x); fma2(acc[2][1], av, b0.y);
            fma2(acc[2][2], av, b1.x); fma2(acc[2][3], av, b1.y);
            av = bc2(a0.w);
            fma2(acc[3][0], av, b0.x); fma2(acc[3][1], av, b0.y);
            fma2(acc[3][2], av, b1.x); fma2(acc[3][3], av, b1.y);
            av = bc2(a1.x);
            fma2(acc[4][0], av, b0.x); fma2(acc[4][1], av, b0.y);
            fma2(acc[4][2], av, b1.x); fma2(acc[4][3], av, b1.y);
            av = bc2(a1.y);
            fma2(acc[5][0], av, b0.x); fma2(acc[5][1], av, b0.y);
            fma2(acc[5][2], av, b1.x); fma2(acc[5][3], av, b1.y);
            av = bc2(a1.z);
            fma2(acc[6][0], av, b0.x); fma2(acc[6][1], av, b0.y);
            fma2(acc[6][2], av, b1.x); fma2(acc[6][3], av, b1.y);
            av = bc2(a1.w);
            fma2(acc[7][0], av, b0.x); fma2(acc[7][1], av, b0.y);
            fma2(acc[7][2], av, b1.x); fma2(acc[7][3], av, b1.y);
        }
        if (kt < 31) {
            const int nxt = cur ^ 1;
            As[nxt][lc + 0][lr] = na.x; As[nxt][lc + 1][lr] = na.y;
            As[nxt][lc + 2][lr] = na.z; As[nxt][lc + 3][lr] = na.w;
            Bs[nxt][lc + 0][lr] = nb.x; Bs[nxt][lc + 1][lr] = nb.y;
            Bs[nxt][lc + 2][lr] = nb.z; Bs[nxt][lc + 3][lr] = nb.w;
            __syncthreads();
        }
    }

    // epilogue: normalize to cosine, vectorized stores
    const float* xn = g_xn + (b << 12);
    const float* yn = g_yn + (b << 12);
    float ynv[8];
#pragma unroll
    for (int j = 0; j < 8; j++) ynv[j] = yn[colBase + bcc + j];
#pragma unroll
    for (int i = 0; i < 8; i++) {
        const int x = rowBase + ar + i;
        const float xv = xn[x];
        float out[8];
#pragma unroll
        for (int j = 0; j < 4; j++) {
            float lo, hi;
            unpk2(acc[i][j], lo, hi);
            out[2 * j]     = lo / (xv * ynv[2 * j] + EPS1);
            out[2 * j + 1] = hi / (xv * ynv[2 * j + 1] + EPS1);
        }
        float* cp = C + (size_t)x * Nn + colBase + bcc;
        *(float4*)cp       = make_float4(out[0], out[1], out[2], out[3]);
        *(float4*)(cp + 4) = make_float4(out[4], out[5], out[6], out[7]);
    }
}

// ---------------- 6. row pass: rowmax(cos), softmax denom --------------------
// d = 1-cos; dmin = 1-cosmax; s = 1/(dmin+eps2)
// w_y = exp(1 - d_y*s) = exp((1-s) + cos_y*s); store s and (1-s)-log(sum w)
__global__ void __launch_bounds__(256) rowpass_kernel() {
    const int r = blockIdx.x;  // b*Nn + x
    const float* row = g_cos + (size_t)r * Nn;
    __shared__ float sh[Nn];
    __shared__ float red[256];
    const int tid = threadIdx.x;
    float m = -1e30f;
#pragma unroll
    for (int j = 0; j < 16; j++) {
        float v = row[tid + (j << 8)];
        sh[tid + (j << 8)] = v;
        m = fmaxf(m, v);
    }
    red[tid] = m;
    __syncthreads();
    for (int st = 128; st > 0; st >>= 1) {
        if (tid < st) red[tid] = fmaxf(red[tid], red[tid + st]);
        __syncthreads();
    }
    const float cmax = red[0];
    __syncthreads();
    const float s = 1.f / (1.f - cmax + EPS2);
    const float a = 1.f - s;
    float sum = 0.f;
#pragma unroll
    for (int j = 0; j < 16; j++) sum += __expf(fmaf(sh[tid + (j << 8)], s, a));
    red[tid] = sum;
    __syncthreads();
    for (int st = 128; st > 0; st >>= 1) {
        if (tid < st) red[tid] += red[tid + st];
        __syncthreads();
    }
    if (tid == 0) {
        g_pS[r] = s;
        g_pA[r] = a - logf(red[0]);
    }
}

// ---------------- 7. column pass: partial max over x (log-domain) ------------
// log c[x][y] = cos*s_x + A_x  -> max over x chunk of 512, no exp per element
__global__ void __launch_bounds__(256) colpass_kernel() {
    const int y = (blockIdx.x << 8) + threadIdx.x;  // 0..4095
    const int chunk = blockIdx.y;                   // 0..7
    const int b = blockIdx.z;                       // 0..3
    __shared__ float ss[512], sa[512];
    const int r0 = (b << 12) + (chunk << 9);
    for (int i = threadIdx.x; i < 512; i += 256) {
        ss[i] = g_pS[r0 + i];
        sa[i] = g_pA[r0 + i];
    }
    __syncthreads();
    const float* base = g_cos + ((size_t)b << 24) + ((size_t)chunk << 21) + y;
    float m = -1e30f;
#pragma unroll 8
    for (int x = 0; x < 512; x++) {
        m = fmaxf(m, fmaf(base[(size_t)x << 12], ss[x], sa[x]));
    }
    g_cmax[(chunk << 14) + (b << 12) + y] = m;
}

// ---------------- 8. final: CS, MSEs, loss -----------------------------------
__global__ void __launch_bounds__(256) final_kernel(float* __restrict__ out) {
    const int tid = threadIdx.x;
    double cs = 0.0;
    for (int i = tid; i < Bn * Nn; i += 256) {
        float m = -1e30f;
#pragma unroll
        for (int ch = 0; ch < 8; ch++) m = fmaxf(m, g_cmax[(ch << 14) + i]);
        cs += exp((double)m);
    }
    double m1 = 0.0, m2 = 0.0;
    for (int i = tid; i < 512; i += 256) {
        m1 += g_msep[0][i];
        m2 += g_msep[1][i];
    }
    __shared__ double sh[3][256];
    sh[0][tid] = cs; sh[1][tid] = m1; sh[2][tid] = m2;
    __syncthreads();
    for (int st = 128; st > 0; st >>= 1) {
        if (tid < st) {
            sh[0][tid] += sh[0][tid + st];
            sh[1][tid] += sh[1][tid + st];
            sh[2][tid] += sh[2][tid + st];
        }
        __syncthreads();
    }
    if (tid == 0) {
        double CS = sh[0][0] / (double)(Bn * Nn);
        double mse1 = sh[1][0] / (double)IMG_ELEMS;
        double perc = sh[2][0] / (double)FEAT_ELEMS;
        out[0] = (float)(mse1 - log(CS) + 0.02 * perc);
    }
}

// ---------------- launch ------------------------------------------------------
extern "C" void kernel_launch(void* const* d_in, const int* in_sizes, int n_in,
                              void* d_out, int out_size) {
    const float* outputs = (const float*)d_in[0];
    const float* targets = (const float*)d_in[1];
    const float* of = (const float*)d_in[2];
    const float* tf = (const float*)d_in[3];
    float* out = (float*)d_out;

    mse_kernel<<<dim3(512, 2), 256>>>(outputs, targets, of, tf);
    mean_kernel<<<dim3(Bn * Cn, 2), 256>>>(of, tf);
    transpose_kernel<<<dim3(Nn / 32, Cn / 32, 2 * Bn), dim3(32, 8)>>>(of, tf);
    norm_kernel<<<dim3(Bn * Nn / 8, 2), 256>>>();
    gemm_kernel<<<dim3(Nn / 128, Nn / 128, Bn), 256>>>();
    rowpass_kernel<<<Bn * Nn, 256>>>();
    colpass_kernel<<<dim3(Nn / 256, 8, Bn), 256>>>();
    final_kernel<<<1, 256>>>(out);
}